// round 1
// baseline (speedup 1.0000x reference)
#include <cuda_runtime.h>
#include <math.h>

#define B_  2
#define L_  2048
#define D_  2048
#define NH_ 16
#define NKV_ 8
#define HD_ 128
#define GQ_ 2
#define SCALE_ 0.08838834764831845f  // 128^-0.5

// Scratch (static device globals — no allocation allowed)
__device__ float g_q[(size_t)B_ * L_ * NH_ * HD_];
__device__ float g_k[(size_t)B_ * L_ * NKV_ * HD_];
__device__ float g_v[(size_t)B_ * L_ * NKV_ * HD_];
__device__ float g_o[(size_t)B_ * L_ * NH_ * HD_];

// ---------------------------------------------------------------------------
// SGEMM: C[M,N] = A[M,K] @ B[N,K]^T   (A,B,C row-major)
// 128x128 block tile, K-tile 16, 256 threads, 8x8 per-thread microtile.
// ---------------------------------------------------------------------------
__global__ void __launch_bounds__(256) sgemm_nt(const float* __restrict__ A,
                                                const float* __restrict__ Bm,
                                                float* __restrict__ C,
                                                int M, int N, int K) {
    __shared__ float As[16][132];
    __shared__ float Bs[16][132];

    const int tid = threadIdx.x;
    const int tx = tid & 15;       // 0..15 -> n microtile
    const int ty = tid >> 4;       // 0..15 -> m microtile
    const int m0 = blockIdx.y * 128;
    const int n0 = blockIdx.x * 128;

    const int lr = tid >> 2;        // 0..63
    const int lc = (tid & 3) << 2;  // 0,4,8,12

    float acc[8][8];
#pragma unroll
    for (int i = 0; i < 8; ++i)
#pragma unroll
        for (int j = 0; j < 8; ++j) acc[i][j] = 0.f;

    for (int k0 = 0; k0 < K; k0 += 16) {
#pragma unroll
        for (int rr = 0; rr < 2; ++rr) {
            const int r = lr + rr * 64;
            float4 a = *(const float4*)(A + (size_t)(m0 + r) * K + k0 + lc);
            As[lc + 0][r] = a.x; As[lc + 1][r] = a.y;
            As[lc + 2][r] = a.z; As[lc + 3][r] = a.w;
            float4 b = *(const float4*)(Bm + (size_t)(n0 + r) * K + k0 + lc);
            Bs[lc + 0][r] = b.x; Bs[lc + 1][r] = b.y;
            Bs[lc + 2][r] = b.z; Bs[lc + 3][r] = b.w;
        }
        __syncthreads();

#pragma unroll
        for (int kk = 0; kk < 16; ++kk) {
            float ar[8], br[8];
            *(float4*)(ar)     = *(const float4*)&As[kk][ty * 8];
            *(float4*)(ar + 4) = *(const float4*)&As[kk][ty * 8 + 4];
            *(float4*)(br)     = *(const float4*)&Bs[kk][tx * 8];
            *(float4*)(br + 4) = *(const float4*)&Bs[kk][tx * 8 + 4];
#pragma unroll
            for (int i = 0; i < 8; ++i)
#pragma unroll
                for (int j = 0; j < 8; ++j) acc[i][j] += ar[i] * br[j];
        }
        __syncthreads();
    }

#pragma unroll
    for (int i = 0; i < 8; ++i) {
        float* cp = C + (size_t)(m0 + ty * 8 + i) * N + n0 + tx * 8;
        float4 o0 = make_float4(acc[i][0], acc[i][1], acc[i][2], acc[i][3]);
        float4 o1 = make_float4(acc[i][4], acc[i][5], acc[i][6], acc[i][7]);
        *(float4*)(cp)     = o0;
        *(float4*)(cp + 4) = o1;
    }
}

// ---------------------------------------------------------------------------
// RoPE in-place on q [B,L,NH,HD] and k [B,L,NKV,HD].
// One thread handles one (b,l,head,i) pair, i in [0,64).
// Angles computed in double to stay well inside 1e-3 rel-err budget.
// ---------------------------------------------------------------------------
__global__ void rope_kernel(float* __restrict__ q, float* __restrict__ k) {
    const long long idx = (long long)blockIdx.x * blockDim.x + threadIdx.x;
    const long long total = (long long)B_ * L_ * (NH_ + NKV_) * 64;
    if (idx >= total) return;

    const int i  = (int)(idx & 63);
    long long r  = idx >> 6;
    const int hh = (int)(r % (NH_ + NKV_));
    r /= (NH_ + NKV_);
    const int bl  = (int)r;          // b*L + l
    const int pos = bl & (L_ - 1);   // l

    float* ptr;
    if (hh < NH_) ptr = q + ((size_t)bl * NH_ + hh) * HD_;
    else          ptr = k + ((size_t)bl * NKV_ + (hh - NH_)) * HD_;

    const double inv = exp(-(double)i / 64.0 * log(10000.0));
    const double ang = (double)pos * inv;
    double sd, cd;
    sincos(ang, &sd, &cd);
    const float c = (float)cd, s = (float)sd;

    const float a = ptr[i];
    const float b = ptr[i + 64];
    ptr[i]      = a * c - b * s;
    ptr[i + 64] = b * c + a * s;
}

// ---------------------------------------------------------------------------
// Flash attention (causal, GQA): one block per (q-tile of 64, head, batch).
// Online softmax, fp32 everywhere.
// smem: Q^T[128][68], K^T[128][68], V[64][128], P[64][68], row stats.
// ---------------------------------------------------------------------------
#define FBM 64
#define FBN 64
#define FPAD 68
#define FLASH_SMEM ((128 * FPAD * 2 + FBN * HD_ + FBM * FPAD + 3 * FBM) * 4)

__global__ void __launch_bounds__(256) flash_attn(const float* __restrict__ Q,
                                                  const float* __restrict__ K,
                                                  const float* __restrict__ V,
                                                  float* __restrict__ O) {
    extern __shared__ float sm[];
    float* QsT   = sm;                       // [128][FPAD]
    float* KsT   = QsT + 128 * FPAD;         // [128][FPAD]
    float* Vs    = KsT + 128 * FPAD;         // [FBN][HD]
    float* Ps    = Vs + FBN * HD_;           // [FBM][FPAD]
    float* row_m = Ps + FBM * FPAD;
    float* row_l = row_m + FBM;
    float* row_a = row_l + FBM;

    const int tid = threadIdx.x;
    const int b = blockIdx.z, h = blockIdx.y;
    const int kvh = h >> 1;                  // GQ = 2
    const int q0 = blockIdx.x * FBM;

    // Load Q tile transposed: QsT[d][r]
    for (int i = tid; i < FBM * 32; i += 256) {
        const int r = i >> 5, d4 = (i & 31) << 2;
        float4 qv = *(const float4*)(Q + ((size_t)(b * L_ + q0 + r) * NH_ + h) * HD_ + d4);
        QsT[(d4 + 0) * FPAD + r] = qv.x;
        QsT[(d4 + 1) * FPAD + r] = qv.y;
        QsT[(d4 + 2) * FPAD + r] = qv.z;
        QsT[(d4 + 3) * FPAD + r] = qv.w;
    }
    if (tid < FBM) { row_m[tid] = -1e30f; row_l[tid] = 0.f; }

    const int ry = tid >> 5;   // 0..7  : owns rows ry*8 .. ry*8+7
    const int rx = tid & 31;   // cols rx*4 .. rx*4+3
    float acc[8][4];
#pragma unroll
    for (int i = 0; i < 8; ++i)
#pragma unroll
        for (int j = 0; j < 4; ++j) acc[i][j] = 0.f;

    __syncthreads();

    const int ty_ = tid >> 4, tx_ = tid & 15;
    const int ktiles = blockIdx.x + 1;

    for (int t = 0; t < ktiles; ++t) {
        const int k0 = t * FBN;

        // Load K^T and V
        for (int i = tid; i < FBN * 32; i += 256) {
            const int r = i >> 5, d4 = (i & 31) << 2;
            const size_t base = ((size_t)(b * L_ + k0 + r) * NKV_ + kvh) * HD_ + d4;
            float4 kv = *(const float4*)(K + base);
            KsT[(d4 + 0) * FPAD + r] = kv.x;
            KsT[(d4 + 1) * FPAD + r] = kv.y;
            KsT[(d4 + 2) * FPAD + r] = kv.z;
            KsT[(d4 + 3) * FPAD + r] = kv.w;
            float4 vv = *(const float4*)(V + base);
            *(float4*)(Vs + r * HD_ + d4) = vv;
        }
        __syncthreads();

        // S = Q @ K^T  (each thread: 4x4 fragment)
        float s[4][4];
#pragma unroll
        for (int a = 0; a < 4; ++a)
#pragma unroll
            for (int c = 0; c < 4; ++c) s[a][c] = 0.f;

        for (int d = 0; d < HD_; ++d) {
            const float4 qa = *(const float4*)(QsT + d * FPAD + ty_ * 4);
            const float4 kb = *(const float4*)(KsT + d * FPAD + tx_ * 4);
            const float qr[4] = {qa.x, qa.y, qa.z, qa.w};
            const float kr[4] = {kb.x, kb.y, kb.z, kb.w};
#pragma unroll
            for (int a = 0; a < 4; ++a)
#pragma unroll
                for (int c = 0; c < 4; ++c) s[a][c] += qr[a] * kr[c];
        }

        // scale + causal mask -> Ps
#pragma unroll
        for (int a = 0; a < 4; ++a) {
            const int gi = q0 + ty_ * 4 + a;
#pragma unroll
            for (int c = 0; c < 4; ++c) {
                const int gj = k0 + tx_ * 4 + c;
                Ps[(ty_ * 4 + a) * FPAD + tx_ * 4 + c] =
                    (gj <= gi) ? s[a][c] * SCALE_ : -1e30f;
            }
        }
        __syncthreads();

        // per-row online softmax stats
        if (tid < FBM) {
            float* pr = Ps + tid * FPAD;
            float mx = row_m[tid];
#pragma unroll 8
            for (int j = 0; j < FBN; ++j) mx = fmaxf(mx, pr[j]);
            const float alpha = __expf(row_m[tid] - mx);
            float sum = 0.f;
#pragma unroll 8
            for (int j = 0; j < FBN; ++j) {
                const float p = __expf(pr[j] - mx);
                pr[j] = p;
                sum += p;
            }
            row_l[tid] = row_l[tid] * alpha + sum;
            row_m[tid] = mx;
            row_a[tid] = alpha;
        }
        __syncthreads();

        // O = alpha*O + P @ V
#pragma unroll
        for (int rr = 0; rr < 8; ++rr) {
            const float al = row_a[ry * 8 + rr];
#pragma unroll
            for (int j = 0; j < 4; ++j) acc[rr][j] *= al;
        }
        for (int m = 0; m < FBN; ++m) {
            const float4 v = *(const float4*)(Vs + m * HD_ + rx * 4);
#pragma unroll
            for (int rr = 0; rr < 8; ++rr) {
                const float p = Ps[(ry * 8 + rr) * FPAD + m];
                acc[rr][0] += p * v.x;
                acc[rr][1] += p * v.y;
                acc[rr][2] += p * v.z;
                acc[rr][3] += p * v.w;
            }
        }
        __syncthreads();
    }

    // epilogue: divide by l, write [b, l, h, d]
#pragma unroll
    for (int rr = 0; rr < 8; ++rr) {
        const int row = ry * 8 + rr;
        const float inv = 1.0f / row_l[row];
        float4 o = make_float4(acc[rr][0] * inv, acc[rr][1] * inv,
                               acc[rr][2] * inv, acc[rr][3] * inv);
        *(float4*)(O + ((size_t)(b * L_ + q0 + row) * NH_ + h) * HD_ + rx * 4) = o;
    }
}

// ---------------------------------------------------------------------------
extern "C" void kernel_launch(void* const* d_in, const int* in_sizes, int n_in,
                              void* d_out, int out_size) {
    const float* x  = (const float*)d_in[0];
    const float* Wq = (const float*)d_in[1];
    const float* Wk = (const float*)d_in[2];
    const float* Wv = (const float*)d_in[3];
    const float* Wo = (const float*)d_in[4];
    float* out = (float*)d_out;

    float *q, *k, *v, *o;
    cudaGetSymbolAddress((void**)&q, g_q);
    cudaGetSymbolAddress((void**)&k, g_k);
    cudaGetSymbolAddress((void**)&v, g_v);
    cudaGetSymbolAddress((void**)&o, g_o);

    const int M = B_ * L_;  // 4096

    // QKV projections
    sgemm_nt<<<dim3(D_ / 128, M / 128), 256>>>(x, Wq, q, M, D_, D_);
    sgemm_nt<<<dim3((NKV_ * HD_) / 128, M / 128), 256>>>(x, Wk, k, M, NKV_ * HD_, D_);
    sgemm_nt<<<dim3((NKV_ * HD_) / 128, M / 128), 256>>>(x, Wv, v, M, NKV_ * HD_, D_);

    // RoPE on q and k
    {
        const long long total = (long long)B_ * L_ * (NH_ + NKV_) * 64;
        const int threads = 256;
        const int blocks = (int)((total + threads - 1) / threads);
        rope_kernel<<<blocks, threads>>>(q, k);
    }

    // Flash attention
    cudaFuncSetAttribute(flash_attn, cudaFuncAttributeMaxDynamicSharedMemorySize,
                         FLASH_SMEM);
    flash_attn<<<dim3(L_ / FBM, NH_, B_), 256, FLASH_SMEM>>>(q, k, v, o);

    // Output projection
    sgemm_nt<<<dim3(D_ / 128, M / 128), 256>>>(o, Wo, out, M, D_, D_);
}

// round 2
// speedup vs baseline: 1.1985x; 1.1985x over previous
#include <cuda_runtime.h>
#include <math.h>

#define B_  2
#define L_  2048
#define D_  2048
#define NH_ 16
#define NKV_ 8
#define HD_ 128
#define GQ_ 2
#define SCALE_ 0.08838834764831845f  // 128^-0.5

// Scratch (static device globals — no allocation allowed)
__device__ float g_q[(size_t)B_ * L_ * NH_ * HD_];
__device__ float g_k[(size_t)B_ * L_ * NKV_ * HD_];
__device__ float g_v[(size_t)B_ * L_ * NKV_ * HD_];
__device__ float g_o[(size_t)B_ * L_ * NH_ * HD_];
__device__ float g_cos[(size_t)L_ * 64];
__device__ float g_sin[(size_t)L_ * 64];

// ---------------------------------------------------------------------------
// SGEMM: C[M,N] = A[M,K] @ B[N,K]^T   (A,B,C row-major)
// 128x128 block tile, K-tile 16, 256 threads, 8x8 per-thread microtile.
// ---------------------------------------------------------------------------
__global__ void __launch_bounds__(256) sgemm_nt(const float* __restrict__ A,
                                                const float* __restrict__ Bm,
                                                float* __restrict__ C,
                                                int M, int N, int K) {
    __shared__ float As[16][132];
    __shared__ float Bs[16][132];

    const int tid = threadIdx.x;
    const int tx = tid & 15;       // 0..15 -> n microtile
    const int ty = tid >> 4;       // 0..15 -> m microtile
    const int m0 = blockIdx.y * 128;
    const int n0 = blockIdx.x * 128;

    const int lr = tid >> 2;        // 0..63
    const int lc = (tid & 3) << 2;  // 0,4,8,12

    float acc[8][8];
#pragma unroll
    for (int i = 0; i < 8; ++i)
#pragma unroll
        for (int j = 0; j < 8; ++j) acc[i][j] = 0.f;

    for (int k0 = 0; k0 < K; k0 += 16) {
#pragma unroll
        for (int rr = 0; rr < 2; ++rr) {
            const int r = lr + rr * 64;
            float4 a = *(const float4*)(A + (size_t)(m0 + r) * K + k0 + lc);
            As[lc + 0][r] = a.x; As[lc + 1][r] = a.y;
            As[lc + 2][r] = a.z; As[lc + 3][r] = a.w;
            float4 b = *(const float4*)(Bm + (size_t)(n0 + r) * K + k0 + lc);
            Bs[lc + 0][r] = b.x; Bs[lc + 1][r] = b.y;
            Bs[lc + 2][r] = b.z; Bs[lc + 3][r] = b.w;
        }
        __syncthreads();

#pragma unroll
        for (int kk = 0; kk < 16; ++kk) {
            float ar[8], br[8];
            *(float4*)(ar)     = *(const float4*)&As[kk][ty * 8];
            *(float4*)(ar + 4) = *(const float4*)&As[kk][ty * 8 + 4];
            *(float4*)(br)     = *(const float4*)&Bs[kk][tx * 8];
            *(float4*)(br + 4) = *(const float4*)&Bs[kk][tx * 8 + 4];
#pragma unroll
            for (int i = 0; i < 8; ++i)
#pragma unroll
                for (int j = 0; j < 8; ++j) acc[i][j] += ar[i] * br[j];
        }
        __syncthreads();
    }

#pragma unroll
    for (int i = 0; i < 8; ++i) {
        float* cp = C + (size_t)(m0 + ty * 8 + i) * N + n0 + tx * 8;
        float4 o0 = make_float4(acc[i][0], acc[i][1], acc[i][2], acc[i][3]);
        float4 o1 = make_float4(acc[i][4], acc[i][5], acc[i][6], acc[i][7]);
        *(float4*)(cp)     = o0;
        *(float4*)(cp + 4) = o1;
    }
}

// ---------------------------------------------------------------------------
// RoPE table: cos/sin for (pos, i), i in [0,64). Double precision once.
// ---------------------------------------------------------------------------
__global__ void rope_table_kernel() {
    const int idx = blockIdx.x * blockDim.x + threadIdx.x;
    if (idx >= L_ * 64) return;
    const int i = idx & 63;
    const int pos = idx >> 6;
    const double inv = exp(-(double)i / 64.0 * log(10000.0));
    double sd, cd;
    sincos((double)pos * inv, &sd, &cd);
    g_cos[idx] = (float)cd;
    g_sin[idx] = (float)sd;
}

// ---------------------------------------------------------------------------
// RoPE apply in-place on q [B,L,NH,HD] and k [B,L,NKV,HD] (memory-bound).
// One thread: one (b,l,head,i) pair, i in [0,64).
// ---------------------------------------------------------------------------
__global__ void rope_apply_kernel(float* __restrict__ q, float* __restrict__ k) {
    const long long idx = (long long)blockIdx.x * blockDim.x + threadIdx.x;
    const long long total = (long long)B_ * L_ * (NH_ + NKV_) * 64;
    if (idx >= total) return;

    const int i  = (int)(idx & 63);
    long long r  = idx >> 6;
    const int hh = (int)(r % (NH_ + NKV_));
    r /= (NH_ + NKV_);
    const int bl  = (int)r;          // b*L + l
    const int pos = bl & (L_ - 1);   // l

    float* ptr;
    if (hh < NH_) ptr = q + ((size_t)bl * NH_ + hh) * HD_;
    else          ptr = k + ((size_t)bl * NKV_ + (hh - NH_)) * HD_;

    const float c = g_cos[pos * 64 + i];
    const float s = g_sin[pos * 64 + i];

    const float a = ptr[i];
    const float b = ptr[i + 64];
    ptr[i]      = a * c - b * s;
    ptr[i + 64] = b * c + a * s;
}

// ---------------------------------------------------------------------------
// Flash attention (causal, GQA): one block per (q-tile of 64, head, batch).
// Online softmax (parallelized: 4 threads/row), fp32 everywhere.
// ---------------------------------------------------------------------------
#define FBM 64
#define FBN 64
#define FPAD 68
#define FLASH_SMEM ((128 * FPAD * 2 + FBN * HD_ + FBM * FPAD + 3 * FBM) * 4)

__global__ void __launch_bounds__(256) flash_attn(const float* __restrict__ Q,
                                                  const float* __restrict__ K,
                                                  const float* __restrict__ V,
                                                  float* __restrict__ O) {
    extern __shared__ float sm[];
    float* QsT   = sm;                       // [128][FPAD]
    float* KsT   = QsT + 128 * FPAD;         // [128][FPAD]
    float* Vs    = KsT + 128 * FPAD;         // [FBN][HD]
    float* Ps    = Vs + FBN * HD_;           // [FBM][FPAD]
    float* row_m = Ps + FBM * FPAD;
    float* row_l = row_m + FBM;
    float* row_a = row_l + FBM;

    const int tid = threadIdx.x;
    const int b = blockIdx.z, h = blockIdx.y;
    const int kvh = h >> 1;                  // GQ = 2
    const int q0 = blockIdx.x * FBM;

    // Load Q tile transposed: QsT[d][r]
    for (int i = tid; i < FBM * 32; i += 256) {
        const int r = i >> 5, d4 = (i & 31) << 2;
        float4 qv = *(const float4*)(Q + ((size_t)(b * L_ + q0 + r) * NH_ + h) * HD_ + d4);
        QsT[(d4 + 0) * FPAD + r] = qv.x;
        QsT[(d4 + 1) * FPAD + r] = qv.y;
        QsT[(d4 + 2) * FPAD + r] = qv.z;
        QsT[(d4 + 3) * FPAD + r] = qv.w;
    }
    if (tid < FBM) { row_m[tid] = -1e30f; row_l[tid] = 0.f; }

    const int ry = tid >> 5;   // 0..7  : owns rows ry*8 .. ry*8+7
    const int rx = tid & 31;   // cols rx*4 .. rx*4+3
    float acc[8][4];
#pragma unroll
    for (int i = 0; i < 8; ++i)
#pragma unroll
        for (int j = 0; j < 4; ++j) acc[i][j] = 0.f;

    __syncthreads();

    const int ty_ = tid >> 4, tx_ = tid & 15;
    const int srow = tid >> 2, ssub = tid & 3;   // softmax: 4 threads per row
    const int ktiles = blockIdx.x + 1;

    for (int t = 0; t < ktiles; ++t) {
        const int k0 = t * FBN;

        // Load K^T and V
        for (int i = tid; i < FBN * 32; i += 256) {
            const int r = i >> 5, d4 = (i & 31) << 2;
            const size_t base = ((size_t)(b * L_ + k0 + r) * NKV_ + kvh) * HD_ + d4;
            float4 kv = *(const float4*)(K + base);
            KsT[(d4 + 0) * FPAD + r] = kv.x;
            KsT[(d4 + 1) * FPAD + r] = kv.y;
            KsT[(d4 + 2) * FPAD + r] = kv.z;
            KsT[(d4 + 3) * FPAD + r] = kv.w;
            float4 vv = *(const float4*)(V + base);
            *(float4*)(Vs + r * HD_ + d4) = vv;
        }
        __syncthreads();

        // S = Q @ K^T  (each thread: 4x4 fragment)
        float s[4][4];
#pragma unroll
        for (int a = 0; a < 4; ++a)
#pragma unroll
            for (int c = 0; c < 4; ++c) s[a][c] = 0.f;

        for (int d = 0; d < HD_; ++d) {
            const float4 qa = *(const float4*)(QsT + d * FPAD + ty_ * 4);
            const float4 kb = *(const float4*)(KsT + d * FPAD + tx_ * 4);
            const float qr[4] = {qa.x, qa.y, qa.z, qa.w};
            const float kr[4] = {kb.x, kb.y, kb.z, kb.w};
#pragma unroll
            for (int a = 0; a < 4; ++a)
#pragma unroll
                for (int c = 0; c < 4; ++c) s[a][c] += qr[a] * kr[c];
        }

        // scale + causal mask -> Ps
        if (t < blockIdx.x) {
            // strictly-lower tile: no masking needed
#pragma unroll
            for (int a = 0; a < 4; ++a)
#pragma unroll
                for (int c = 0; c < 4; ++c)
                    Ps[(ty_ * 4 + a) * FPAD + tx_ * 4 + c] = s[a][c] * SCALE_;
        } else {
#pragma unroll
            for (int a = 0; a < 4; ++a) {
                const int gi = q0 + ty_ * 4 + a;
#pragma unroll
                for (int c = 0; c < 4; ++c) {
                    const int gj = k0 + tx_ * 4 + c;
                    Ps[(ty_ * 4 + a) * FPAD + tx_ * 4 + c] =
                        (gj <= gi) ? s[a][c] * SCALE_ : -1e30f;
                }
            }
        }
        __syncthreads();

        // online softmax: 4 threads per row, 16 cols each, shuffle-reduce
        {
            float* pr = Ps + srow * FPAD + ssub * 16;
            float4 pv[4];
#pragma unroll
            for (int j = 0; j < 4; ++j) pv[j] = *(const float4*)(pr + j * 4);

            float mx = -1e30f;
#pragma unroll
            for (int j = 0; j < 4; ++j) {
                mx = fmaxf(mx, fmaxf(fmaxf(pv[j].x, pv[j].y), fmaxf(pv[j].z, pv[j].w)));
            }
            mx = fmaxf(mx, __shfl_xor_sync(0xffffffffu, mx, 1));
            mx = fmaxf(mx, __shfl_xor_sync(0xffffffffu, mx, 2));
            const float old_m = row_m[srow];
            mx = fmaxf(mx, old_m);

            float sum = 0.f;
#pragma unroll
            for (int j = 0; j < 4; ++j) {
                pv[j].x = __expf(pv[j].x - mx); sum += pv[j].x;
                pv[j].y = __expf(pv[j].y - mx); sum += pv[j].y;
                pv[j].z = __expf(pv[j].z - mx); sum += pv[j].z;
                pv[j].w = __expf(pv[j].w - mx); sum += pv[j].w;
                *(float4*)(pr + j * 4) = pv[j];
            }
            sum += __shfl_xor_sync(0xffffffffu, sum, 1);
            sum += __shfl_xor_sync(0xffffffffu, sum, 2);

            if (ssub == 0) {
                const float alpha = __expf(old_m - mx);
                row_l[srow] = row_l[srow] * alpha + sum;
                row_m[srow] = mx;
                row_a[srow] = alpha;
            }
        }
        __syncthreads();

        // O = alpha*O + P @ V
#pragma unroll
        for (int rr = 0; rr < 8; ++rr) {
            const float al = row_a[ry * 8 + rr];
#pragma unroll
            for (int j = 0; j < 4; ++j) acc[rr][j] *= al;
        }
        for (int m = 0; m < FBN; ++m) {
            const float4 v = *(const float4*)(Vs + m * HD_ + rx * 4);
#pragma unroll
            for (int rr = 0; rr < 8; ++rr) {
                const float p = Ps[(ry * 8 + rr) * FPAD + m];
                acc[rr][0] += p * v.x;
                acc[rr][1] += p * v.y;
                acc[rr][2] += p * v.z;
                acc[rr][3] += p * v.w;
            }
        }
        __syncthreads();
    }

    // epilogue: divide by l, write [b, l, h, d]
#pragma unroll
    for (int rr = 0; rr < 8; ++rr) {
        const int row = ry * 8 + rr;
        const float inv = 1.0f / row_l[row];
        float4 o = make_float4(acc[rr][0] * inv, acc[rr][1] * inv,
                               acc[rr][2] * inv, acc[rr][3] * inv);
        *(float4*)(O + ((size_t)(b * L_ + q0 + row) * NH_ + h) * HD_ + rx * 4) = o;
    }
}

// ---------------------------------------------------------------------------
extern "C" void kernel_launch(void* const* d_in, const int* in_sizes, int n_in,
                              void* d_out, int out_size) {
    const float* x  = (const float*)d_in[0];
    const float* Wq = (const float*)d_in[1];
    const float* Wk = (const float*)d_in[2];
    const float* Wv = (const float*)d_in[3];
    const float* Wo = (const float*)d_in[4];
    float* out = (float*)d_out;

    float *q, *k, *v, *o;
    cudaGetSymbolAddress((void**)&q, g_q);
    cudaGetSymbolAddress((void**)&k, g_k);
    cudaGetSymbolAddress((void**)&v, g_v);
    cudaGetSymbolAddress((void**)&o, g_o);

    const int M = B_ * L_;  // 4096

    // RoPE table (independent of projections — overlaps fine)
    rope_table_kernel<<<(L_ * 64 + 255) / 256, 256>>>();

    // QKV projections
    sgemm_nt<<<dim3(D_ / 128, M / 128), 256>>>(x, Wq, q, M, D_, D_);
    sgemm_nt<<<dim3((NKV_ * HD_) / 128, M / 128), 256>>>(x, Wk, k, M, NKV_ * HD_, D_);
    sgemm_nt<<<dim3((NKV_ * HD_) / 128, M / 128), 256>>>(x, Wv, v, M, NKV_ * HD_, D_);

    // RoPE apply on q and k
    {
        const long long total = (long long)B_ * L_ * (NH_ + NKV_) * 64;
        const int threads = 256;
        const int blocks = (int)((total + threads - 1) / threads);
        rope_apply_kernel<<<blocks, threads>>>(q, k);
    }

    // Flash attention
    cudaFuncSetAttribute(flash_attn, cudaFuncAttributeMaxDynamicSharedMemorySize,
                         FLASH_SMEM);
    flash_attn<<<dim3(L_ / FBM, NH_, B_), 256, FLASH_SMEM>>>(q, k, v, o);

    // Output projection
    sgemm_nt<<<dim3(D_ / 128, M / 128), 256>>>(o, Wo, out, M, D_, D_);
}

// round 3
// speedup vs baseline: 1.2431x; 1.0373x over previous
#include <cuda_runtime.h>
#include <math.h>

#define B_  2
#define L_  2048
#define D_  2048
#define NH_ 16
#define NKV_ 8
#define HD_ 128
#define GQ_ 2
#define SCALE_ 0.08838834764831845f  // 128^-0.5

// Scratch (static device globals — no allocation allowed)
__device__ float g_q[(size_t)B_ * L_ * NH_ * HD_];
__device__ float g_k[(size_t)B_ * L_ * NKV_ * HD_];
__device__ float g_v[(size_t)B_ * L_ * NKV_ * HD_];
__device__ float g_o[(size_t)B_ * L_ * NH_ * HD_];
__device__ float g_cos[(size_t)L_ * 64];
__device__ float g_sin[(size_t)L_ * 64];

// ---------------------------------------------------------------------------
// SGEMM: C[M,N] = A[M,K] @ B[N,K]^T   (A,B,C row-major)
// ---------------------------------------------------------------------------
__global__ void __launch_bounds__(256) sgemm_nt(const float* __restrict__ A,
                                                const float* __restrict__ Bm,
                                                float* __restrict__ C,
                                                int M, int N, int K) {
    __shared__ float As[16][132];
    __shared__ float Bs[16][132];

    const int tid = threadIdx.x;
    const int tx = tid & 15;
    const int ty = tid >> 4;
    const int m0 = blockIdx.y * 128;
    const int n0 = blockIdx.x * 128;

    const int lr = tid >> 2;
    const int lc = (tid & 3) << 2;

    float acc[8][8];
#pragma unroll
    for (int i = 0; i < 8; ++i)
#pragma unroll
        for (int j = 0; j < 8; ++j) acc[i][j] = 0.f;

    for (int k0 = 0; k0 < K; k0 += 16) {
#pragma unroll
        for (int rr = 0; rr < 2; ++rr) {
            const int r = lr + rr * 64;
            float4 a = *(const float4*)(A + (size_t)(m0 + r) * K + k0 + lc);
            As[lc + 0][r] = a.x; As[lc + 1][r] = a.y;
            As[lc + 2][r] = a.z; As[lc + 3][r] = a.w;
            float4 b = *(const float4*)(Bm + (size_t)(n0 + r) * K + k0 + lc);
            Bs[lc + 0][r] = b.x; Bs[lc + 1][r] = b.y;
            Bs[lc + 2][r] = b.z; Bs[lc + 3][r] = b.w;
        }
        __syncthreads();

#pragma unroll
        for (int kk = 0; kk < 16; ++kk) {
            float ar[8], br[8];
            *(float4*)(ar)     = *(const float4*)&As[kk][ty * 8];
            *(float4*)(ar + 4) = *(const float4*)&As[kk][ty * 8 + 4];
            *(float4*)(br)     = *(const float4*)&Bs[kk][tx * 8];
            *(float4*)(br + 4) = *(const float4*)&Bs[kk][tx * 8 + 4];
#pragma unroll
            for (int i = 0; i < 8; ++i)
#pragma unroll
                for (int j = 0; j < 8; ++j) acc[i][j] += ar[i] * br[j];
        }
        __syncthreads();
    }

#pragma unroll
    for (int i = 0; i < 8; ++i) {
        float* cp = C + (size_t)(m0 + ty * 8 + i) * N + n0 + tx * 8;
        *(float4*)(cp)     = make_float4(acc[i][0], acc[i][1], acc[i][2], acc[i][3]);
        *(float4*)(cp + 4) = make_float4(acc[i][4], acc[i][5], acc[i][6], acc[i][7]);
    }
}

// ---------------------------------------------------------------------------
// RoPE table + apply
// ---------------------------------------------------------------------------
__global__ void rope_table_kernel() {
    const int idx = blockIdx.x * blockDim.x + threadIdx.x;
    if (idx >= L_ * 64) return;
    const int i = idx & 63;
    const int pos = idx >> 6;
    const double inv = exp(-(double)i / 64.0 * log(10000.0));
    double sd, cd;
    sincos((double)pos * inv, &sd, &cd);
    g_cos[idx] = (float)cd;
    g_sin[idx] = (float)sd;
}

__global__ void rope_apply_kernel(float* __restrict__ q, float* __restrict__ k) {
    const long long idx = (long long)blockIdx.x * blockDim.x + threadIdx.x;
    const long long total = (long long)B_ * L_ * (NH_ + NKV_) * 64;
    if (idx >= total) return;

    const int i  = (int)(idx & 63);
    long long r  = idx >> 6;
    const int hh = (int)(r % (NH_ + NKV_));
    r /= (NH_ + NKV_);
    const int bl  = (int)r;
    const int pos = bl & (L_ - 1);

    float* ptr;
    if (hh < NH_) ptr = q + ((size_t)bl * NH_ + hh) * HD_;
    else          ptr = k + ((size_t)bl * NKV_ + (hh - NH_)) * HD_;

    const float c = g_cos[pos * 64 + i];
    const float s = g_sin[pos * 64 + i];
    const float a = ptr[i];
    const float b = ptr[i + 64];
    ptr[i]      = a * c - b * s;
    ptr[i + 64] = b * c + a * s;
}

// ---------------------------------------------------------------------------
// Flash attention v2: fused double-sgemm.
// Block: 256 threads. Q-tile 128 rows, K-tile 64 cols.
// Phase 1: S^T[c][r] = K @ Q^T, sgemm-style 16-deep d-slices (reg prefetch).
// Phase 2: softmax over columns of S^T (rows of S), online stats.
// Phase 3: O[r][d] += P^T-slices @ V-slices (TN outer-product stream).
// ---------------------------------------------------------------------------
__global__ void __launch_bounds__(256) flash_attn2(const float* __restrict__ Q,
                                                   const float* __restrict__ K,
                                                   const float* __restrict__ V,
                                                   float* __restrict__ O) {
    __shared__ float St[64 * 132];    // S^T then P^T  [c][r], pitch 132
    __shared__ float QVs[16 * 132];   // Q^T d-slice / V c-slice
    __shared__ float Ks[16 * 68];     // K^T d-slice
    __shared__ float row_m[128], row_l[128], row_a[128];

    const int tid = threadIdx.x;
    const int b = blockIdx.z, h = blockIdx.y;
    const int kvh = h >> 1;
    const int qt = (gridDim.x - 1) - blockIdx.x;   // heavy tiles first
    const int q0 = qt * 128;

    // staging ids
    const int lr = tid >> 2;             // 0..63
    const int lc = (tid & 3) << 2;       // 0,4,8,12
    const int vrow = tid >> 5;           // 0..7
    const int vcol = (tid & 31) << 2;    // 0..124

    // S-phase compute ids: c-block 4 (tid>>4), r-block 8 (tid&15)
    const int cb = (tid >> 4) << 2;
    const int rb = (tid & 15) << 3;
    // PV-phase ids: r-block 8 (tid>>4), d-block 8 (tid&15)
    const int prb = (tid >> 4) << 3;
    const int pdb = (tid & 15) << 3;

    const float* Qg = Q + ((size_t)(b * L_ + q0) * NH_ + h) * HD_;   // row stride NH_*HD_
    const float* Kg = K + ((size_t)(b * L_) * NKV_ + kvh) * HD_;     // row stride NKV_*HD_
    const float* Vg = V + ((size_t)(b * L_) * NKV_ + kvh) * HD_;

    if (tid < 128) { row_m[tid] = -1e30f; row_l[tid] = 0.f; }

    float acc_o[8][8];
#pragma unroll
    for (int i = 0; i < 8; ++i)
#pragma unroll
        for (int j = 0; j < 8; ++j) acc_o[i][j] = 0.f;

    const int tmax = 2 * qt + 2;
    for (int t = 0; t < tmax; ++t) {
        const int k0 = t * 64;

        // ---------------- Phase 1: S^T = K @ Q^T ----------------
        float acc_s[4][8];
#pragma unroll
        for (int j = 0; j < 4; ++j)
#pragma unroll
            for (int i = 0; i < 8; ++i) acc_s[j][i] = 0.f;

        float4 kp  = *(const float4*)(Kg + (size_t)(k0 + lr) * (NKV_ * HD_) + lc);
        float4 qp0 = *(const float4*)(Qg + (size_t)lr        * (NH_ * HD_) + lc);
        float4 qp1 = *(const float4*)(Qg + (size_t)(lr + 64) * (NH_ * HD_) + lc);

        for (int d0 = 0; d0 < HD_; d0 += 16) {
            __syncthreads();
            Ks[(lc + 0) * 68 + lr] = kp.x;  Ks[(lc + 1) * 68 + lr] = kp.y;
            Ks[(lc + 2) * 68 + lr] = kp.z;  Ks[(lc + 3) * 68 + lr] = kp.w;
            QVs[(lc + 0) * 132 + lr] = qp0.x;  QVs[(lc + 1) * 132 + lr] = qp0.y;
            QVs[(lc + 2) * 132 + lr] = qp0.z;  QVs[(lc + 3) * 132 + lr] = qp0.w;
            QVs[(lc + 0) * 132 + lr + 64] = qp1.x;  QVs[(lc + 1) * 132 + lr + 64] = qp1.y;
            QVs[(lc + 2) * 132 + lr + 64] = qp1.z;  QVs[(lc + 3) * 132 + lr + 64] = qp1.w;
            __syncthreads();

            if (d0 + 16 < HD_) {
                kp  = *(const float4*)(Kg + (size_t)(k0 + lr) * (NKV_ * HD_) + d0 + 16 + lc);
                qp0 = *(const float4*)(Qg + (size_t)lr        * (NH_ * HD_) + d0 + 16 + lc);
                qp1 = *(const float4*)(Qg + (size_t)(lr + 64) * (NH_ * HD_) + d0 + 16 + lc);
            }

#pragma unroll
            for (int kk = 0; kk < 16; ++kk) {
                float kr[4], qr[8];
                *(float4*)(kr)     = *(const float4*)&Ks[kk * 68 + cb];
                *(float4*)(qr)     = *(const float4*)&QVs[kk * 132 + rb];
                *(float4*)(qr + 4) = *(const float4*)&QVs[kk * 132 + rb + 4];
#pragma unroll
                for (int j = 0; j < 4; ++j)
#pragma unroll
                    for (int i = 0; i < 8; ++i) acc_s[j][i] += kr[j] * qr[i];
            }
        }

        // store scaled + masked S^T (float4 along r)
        __syncthreads();
#pragma unroll
        for (int j = 0; j < 4; ++j) {
            const int thr = (k0 + cb + j) - (q0 + rb);   // valid iff i >= thr
#pragma unroll
            for (int ih = 0; ih < 2; ++ih) {
                float4 o;
                o.x = (ih * 4 + 0 >= thr) ? acc_s[j][ih * 4 + 0] * SCALE_ : -1e30f;
                o.y = (ih * 4 + 1 >= thr) ? acc_s[j][ih * 4 + 1] * SCALE_ : -1e30f;
                o.z = (ih * 4 + 2 >= thr) ? acc_s[j][ih * 4 + 2] * SCALE_ : -1e30f;
                o.w = (ih * 4 + 3 >= thr) ? acc_s[j][ih * 4 + 3] * SCALE_ : -1e30f;
                *(float4*)&St[(cb + j) * 132 + rb + ih * 4] = o;
            }
        }
        __syncthreads();

        // ---------------- Phase 2: online softmax (per q-row) ----------------
        {
            const int r = tid >> 1, sub = tid & 1;
            float* colp = St + r + (sub << 5) * 132;
            float mx = -1e30f;
#pragma unroll 8
            for (int c = 0; c < 32; ++c) mx = fmaxf(mx, colp[c * 132]);
            mx = fmaxf(mx, __shfl_xor_sync(0xffffffffu, mx, 1));
            const float oldm = row_m[r];
            const float nm = fmaxf(mx, oldm);
            float sum = 0.f;
#pragma unroll 8
            for (int c = 0; c < 32; ++c) {
                const float p = __expf(colp[c * 132] - nm);
                colp[c * 132] = p;
                sum += p;
            }
            sum += __shfl_xor_sync(0xffffffffu, sum, 1);
            if (sub == 0) {
                const float al = __expf(oldm - nm);
                row_a[r] = al;
                row_l[r] = row_l[r] * al + sum;
                row_m[r] = nm;
            }
        }
        __syncthreads();

        // ---------------- Phase 3: O = alpha*O + P^T-slices @ V ----------------
#pragma unroll
        for (int i = 0; i < 8; ++i) {
            const float al = row_a[prb + i];
#pragma unroll
            for (int j = 0; j < 8; ++j) acc_o[i][j] *= al;
        }

        float4 vp0 = *(const float4*)(Vg + (size_t)(k0 + vrow)     * (NKV_ * HD_) + vcol);
        float4 vp1 = *(const float4*)(Vg + (size_t)(k0 + vrow + 8) * (NKV_ * HD_) + vcol);

        for (int c0 = 0; c0 < 64; c0 += 16) {
            __syncthreads();
            *(float4*)&QVs[vrow * 132 + vcol]       = vp0;
            *(float4*)&QVs[(vrow + 8) * 132 + vcol] = vp1;
            __syncthreads();

            if (c0 + 16 < 64) {
                vp0 = *(const float4*)(Vg + (size_t)(k0 + c0 + 16 + vrow)     * (NKV_ * HD_) + vcol);
                vp1 = *(const float4*)(Vg + (size_t)(k0 + c0 + 16 + vrow + 8) * (NKV_ * HD_) + vcol);
            }

#pragma unroll
            for (int cc = 0; cc < 16; ++cc) {
                float p8[8], v8[8];
                *(float4*)(p8)     = *(const float4*)&St[(c0 + cc) * 132 + prb];
                *(float4*)(p8 + 4) = *(const float4*)&St[(c0 + cc) * 132 + prb + 4];
                *(float4*)(v8)     = *(const float4*)&QVs[cc * 132 + pdb];
                *(float4*)(v8 + 4) = *(const float4*)&QVs[cc * 132 + pdb + 4];
#pragma unroll
                for (int i = 0; i < 8; ++i)
#pragma unroll
                    for (int j = 0; j < 8; ++j) acc_o[i][j] += p8[i] * v8[j];
            }
        }
    }

    // epilogue: divide by l, write O[b, q0+r, h, d]
#pragma unroll
    for (int i = 0; i < 8; ++i) {
        const float inv = 1.0f / row_l[prb + i];
        float* op = O + ((size_t)(b * L_ + q0 + prb + i) * NH_ + h) * HD_ + pdb;
        *(float4*)(op)     = make_float4(acc_o[i][0] * inv, acc_o[i][1] * inv,
                                         acc_o[i][2] * inv, acc_o[i][3] * inv);
        *(float4*)(op + 4) = make_float4(acc_o[i][4] * inv, acc_o[i][5] * inv,
                                         acc_o[i][6] * inv, acc_o[i][7] * inv);
    }
}

// ---------------------------------------------------------------------------
extern "C" void kernel_launch(void* const* d_in, const int* in_sizes, int n_in,
                              void* d_out, int out_size) {
    const float* x  = (const float*)d_in[0];
    const float* Wq = (const float*)d_in[1];
    const float* Wk = (const float*)d_in[2];
    const float* Wv = (const float*)d_in[3];
    const float* Wo = (const float*)d_in[4];
    float* out = (float*)d_out;

    float *q, *k, *v, *o;
    cudaGetSymbolAddress((void**)&q, g_q);
    cudaGetSymbolAddress((void**)&k, g_k);
    cudaGetSymbolAddress((void**)&v, g_v);
    cudaGetSymbolAddress((void**)&o, g_o);

    const int M = B_ * L_;  // 4096

    rope_table_kernel<<<(L_ * 64 + 255) / 256, 256>>>();

    sgemm_nt<<<dim3(D_ / 128, M / 128), 256>>>(x, Wq, q, M, D_, D_);
    sgemm_nt<<<dim3((NKV_ * HD_) / 128, M / 128), 256>>>(x, Wk, k, M, NKV_ * HD_, D_);
    sgemm_nt<<<dim3((NKV_ * HD_) / 128, M / 128), 256>>>(x, Wv, v, M, NKV_ * HD_, D_);

    {
        const long long total = (long long)B_ * L_ * (NH_ + NKV_) * 64;
        const int blocks = (int)((total + 255) / 256);
        rope_apply_kernel<<<blocks, 256>>>(q, k);
    }

    flash_attn2<<<dim3(L_ / 128, NH_, B_), 256>>>(q, k, v, o);

    sgemm_nt<<<dim3(D_ / 128, M / 128), 256>>>(o, Wo, out, M, D_, D_);
}